// round 11
// baseline (speedup 1.0000x reference)
#include <cuda_runtime.h>
#include <cuda_bf16.h>
#include <math.h>
#include <stdint.h>

#define BATCH  128
#define SEQL   512
#define EMBED  512
#define HIDDEN 1024
#define NCLS   1000
#define NTOT   2048

#define NCTA   128
#define KSPLIT 4

typedef unsigned long long ull;
typedef unsigned int u32;

// ---------------- device scratch -----------------------------------------------
__device__ float g_X[2][SEQL][BATCH * HIDDEN];     // x_t @ W_in + b, per gate
__device__ float g_P[KSPLIT][BATCH * NTOT];        // k-split partials
__device__ __nv_bfloat16 g_hhi[2][BATCH * HIDDEN]; // h state, bf16 hi (ping-pong)
__device__ __nv_bfloat16 g_hlo[2][BATCH * HIDDEN]; // h state, bf16 lo
__device__ __nv_bfloat16 g_Wt_hi[NTOT * HIDDEN];   // recurrent W^T hi  [n][k]
__device__ __nv_bfloat16 g_Wt_lo[NTOT * HIDDEN];
__device__ __nv_bfloat16 g_Win_hi[NTOT * EMBED];   // input-proj W^T hi [n][k]
__device__ __nv_bfloat16 g_Win_lo[NTOT * EMBED];
__device__ __nv_bfloat16 g_emb_hi[32000 * EMBED];  // emb table bf16 hi
__device__ __nv_bfloat16 g_emb_lo[32000 * EMBED];

__device__ unsigned g_flags[NCTA];     // full barrier arrive flags
__device__ unsigned g_release;         // full barrier release word
__device__ unsigned g_flags2[NCTA];    // neighborhood barrier flags

// ---------------- MMA / ldmatrix / cp.async helpers ----------------------------
__device__ __forceinline__ u32 smem_u32(const void* p) {
    u32 a;
    asm("{ .reg .u64 t; cvta.to.shared.u64 t, %1; cvt.u32.u64 %0, t; }" : "=r"(a) : "l"(p));
    return a;
}
__device__ __forceinline__ void ldmx4(u32* r, u32 addr) {
    asm volatile("ldmatrix.sync.aligned.m8n8.x4.shared.b16 {%0,%1,%2,%3}, [%4];"
                 : "=r"(r[0]), "=r"(r[1]), "=r"(r[2]), "=r"(r[3]) : "r"(addr));
}
__device__ __forceinline__ void mma16816(float* c, const u32* a, u32 b0, u32 b1) {
    asm volatile("mma.sync.aligned.m16n8k16.row.col.f32.bf16.bf16.f32 "
                 "{%0,%1,%2,%3}, {%4,%5,%6,%7}, {%8,%9}, {%0,%1,%2,%3};"
                 : "+f"(c[0]), "+f"(c[1]), "+f"(c[2]), "+f"(c[3])
                 : "r"(a[0]), "r"(a[1]), "r"(a[2]), "r"(a[3]), "r"(b0), "r"(b1));
}
#define CP16(dst, src) \
    asm volatile("cp.async.cg.shared.global [%0], [%1], 16;" :: "r"(dst), "l"(src) : "memory")
#define CP_COMMIT() asm volatile("cp.async.commit_group;" ::: "memory")
#define CP_WAIT1()  asm volatile("cp.async.wait_group 1;" ::: "memory")
#define CP_WAIT0()  asm volatile("cp.async.wait_group 0;" ::: "memory")

// ---------------- full barrier (two-stage: flags -> CTA0 -> release) ------------
__device__ __forceinline__ void full_barrier(int cta, unsigned gen) {
    __syncthreads();
    if (threadIdx.x == 0) {
        __threadfence();
        *((volatile unsigned*)&g_flags[cta]) = gen;
    }
    if (cta == 0) {
        if (threadIdx.x < NCTA) {
            while (*((volatile unsigned*)&g_flags[threadIdx.x]) < gen) { }
        }
        __syncthreads();
        if (threadIdx.x == 0) {
            __threadfence();
            *((volatile unsigned*)&g_release) = gen;
        }
    }
    if (threadIdx.x == 0) {
        while (*((volatile unsigned*)&g_release) < gen) { }
        __threadfence();
    }
    __syncthreads();
}

// ---------------- neighborhood barrier: the 8 CTAs sharing h-col tile j ---------
// group(j) = {4j..4j+3} u {64+4j..64+4j+3}; all arrive, all poll the 8 flags.
__device__ __forceinline__ void nb_barrier(int cta, int j, unsigned gen) {
    __syncthreads();
    if (threadIdx.x == 0) {
        __threadfence();
        *((volatile unsigned*)&g_flags2[cta]) = gen;
    }
    if (threadIdx.x < 8) {
        int idx = (threadIdx.x < 4) ? (4 * j + threadIdx.x)
                                    : (64 + 4 * j + (threadIdx.x - 4));
        while (*((volatile unsigned*)&g_flags2[idx]) < gen) { }
        __threadfence();
    }
    __syncthreads();
}

// ---------------- init ------------------------------------------------------------
__global__ void init_kernel() {
    int i = blockIdx.x * 256 + threadIdx.x;           // 0..131071
    __nv_bfloat16 z = __float2bfloat16(0.0f);
    g_hhi[0][i] = z; g_hhi[1][i] = z;
    g_hlo[0][i] = z; g_hlo[1][i] = z;
    if (i < NCTA) { g_flags[i] = 0; g_flags2[i] = 0; }
    if (i == 0) g_release = 0;
}

// ---------------- emb table -> bf16 hi/lo ------------------------------------------
__global__ void conv_emb(const float* __restrict__ emb) {
    long i = (long)blockIdx.x * 256 + threadIdx.x;
    float4 v = *(const float4*)&emb[i * 4];
    float f[4] = {v.x, v.y, v.z, v.w};
    unsigned short hiu[4], lou[4];
#pragma unroll
    for (int j = 0; j < 4; j++) {
        __nv_bfloat16 hb = __float2bfloat16_rn(f[j]);
        __nv_bfloat16 lb = __float2bfloat16_rn(f[j] - __bfloat162float(hb));
        hiu[j] = __bfloat16_as_ushort(hb);
        lou[j] = __bfloat16_as_ushort(lb);
    }
    *(ull*)&g_emb_hi[i * 4] = (ull)hiu[0] | ((ull)hiu[1] << 16) | ((ull)hiu[2] << 32) | ((ull)hiu[3] << 48);
    *(ull*)&g_emb_lo[i * 4] = (ull)lou[0] | ((ull)lou[1] << 16) | ((ull)lou[2] << 32) | ((ull)lou[3] << 48);
}

// ---------------- weight prep: recurrent part (k in [512,1536)) --------------------
__global__ void prep_weights(const float* __restrict__ Wz,
                             const float* __restrict__ Wh)
{
    __shared__ float tile[32][33];
    const int k0  = blockIdx.x * 32;
    const int n0g = blockIdx.y * 32;
    const float* W = (n0g < 1024) ? Wz : Wh;
    const int nc0 = n0g & 1023;

    for (int r = threadIdx.y; r < 32; r += 8)
        tile[r][threadIdx.x] = W[(long)(512 + k0 + r) * HIDDEN + nc0 + threadIdx.x];
    __syncthreads();
    for (int r2 = threadIdx.y; r2 < 32; r2 += 8) {
        float v = tile[threadIdx.x][r2];
        __nv_bfloat16 hi = __float2bfloat16_rn(v);
        __nv_bfloat16 lo = __float2bfloat16_rn(v - __bfloat162float(hi));
        long o = (long)(n0g + r2) * HIDDEN + k0 + threadIdx.x;
        g_Wt_hi[o] = hi;
        g_Wt_lo[o] = lo;
    }
}

// ---------------- weight prep: input part (k in [0,512)) ---------------------------
__global__ void prep_win(const float* __restrict__ Wz,
                         const float* __restrict__ Wh)
{
    __shared__ float tile[32][33];
    const int k0  = blockIdx.x * 32;
    const int n0g = blockIdx.y * 32;
    const float* W = (n0g < 1024) ? Wz : Wh;
    const int nc0 = n0g & 1023;

    for (int r = threadIdx.y; r < 32; r += 8)
        tile[r][threadIdx.x] = W[(long)(k0 + r) * HIDDEN + nc0 + threadIdx.x];
    __syncthreads();
    for (int r2 = threadIdx.y; r2 < 32; r2 += 8) {
        float v = tile[threadIdx.x][r2];
        __nv_bfloat16 hi = __float2bfloat16_rn(v);
        __nv_bfloat16 lo = __float2bfloat16_rn(v - __bfloat162float(hi));
        long o = (long)(n0g + r2) * EMBED + k0 + threadIdx.x;
        g_Win_hi[o] = hi;
        g_Win_lo[o] = lo;
    }
}

// ---------------- Kernel 1: HMMA embedding projection ------------------------------
#define E_STRB 144
#define E_MAT  18432
#define E_BUF  (4 * E_MAT)
#define E_SIDX (2 * E_BUF)
#define SMEM_EMBED (E_SIDX + 512)

__global__ __launch_bounds__(256, 1) void gemm_embed_mma(
    const int*   __restrict__ x,
    const float* __restrict__ bz,
    const float* __restrict__ bh)
{
    extern __shared__ char smem[];
    const u32 sbase = smem_u32(smem);
    const int tid = threadIdx.x;
    const int wid = tid >> 5, lane = tid & 31;
    const int n0 = blockIdx.x * 128;
    const int m0 = blockIdx.y * 128;

    int* sidx = (int*)(smem + E_SIDX);
    if (tid < 128) sidx[tid] = x[m0 + tid];
    __syncthreads();

    const int srow[4] = { (tid + 0)   >> 3, (tid + 256) >> 3,
                          (tid + 512) >> 3, (tid + 768) >> 3 };
    const int sc = tid & 7;

    auto issue_tile = [&](int kt, int b) {
        const int k0 = kt * 64;
#pragma unroll
        for (int j = 0; j < 4; j++) {
            int row = srow[j];
            u32 dst = sbase + b * E_BUF + row * E_STRB + sc * 16;
            long aoff = (long)sidx[row] * EMBED + k0 + sc * 8;
            long boff = (long)(n0 + row) * EMBED + k0 + sc * 8;
            CP16(dst,             (const void*)&g_emb_hi[aoff]);
            CP16(dst + E_MAT,     (const void*)&g_emb_lo[aoff]);
            CP16(dst + 2 * E_MAT, (const void*)&g_Win_hi[boff]);
            CP16(dst + 3 * E_MAT, (const void*)&g_Win_lo[boff]);
        }
        CP_COMMIT();
    };

    const int m_base = (wid & 3) * 32;
    const int n_base = (wid >> 2) * 64;
    const u32 a_row = (u32)(lane & 15);
    const u32 b_row = (u32)((((lane >> 3) & 1) * 8) + (lane & 7));
    const u32 khalf = (u32)((lane >> 4) * 16);

    float c[2][8][4];
#pragma unroll
    for (int mi = 0; mi < 2; mi++)
#pragma unroll
        for (int nf = 0; nf < 8; nf++)
#pragma unroll
            for (int r = 0; r < 4; r++) c[mi][nf][r] = 0.0f;

    issue_tile(0, 0);

    for (int kt = 0; kt < 8; kt++) {
        if (kt < 7) { issue_tile(kt + 1, (kt + 1) & 1); CP_WAIT1(); }
        else        { CP_WAIT0(); }
        __syncthreads();

        const u32 base = sbase + (kt & 1) * E_BUF;
#pragma unroll
        for (int k16 = 0; k16 < 4; k16++) {
            const u32 kb = (u32)(k16 * 32) + khalf;
            u32 ah[2][4], al[2][4], bhv[4][4], blv[4][4];
#pragma unroll
            for (int mi = 0; mi < 2; mi++) {
                u32 ar = base + (m_base + mi * 16 + a_row) * E_STRB + kb;
                ldmx4(ah[mi], ar);
                ldmx4(al[mi], ar + E_MAT);
            }
#pragma unroll
            for (int nb = 0; nb < 4; nb++) {
                u32 br = base + 2 * E_MAT + (n_base + nb * 16 + b_row) * E_STRB + kb;
                ldmx4(bhv[nb], br);
                ldmx4(blv[nb], br + E_MAT);
            }
#pragma unroll
            for (int mi = 0; mi < 2; mi++) {
#pragma unroll
                for (int nf = 0; nf < 8; nf++) {
                    int nb = nf >> 1, hf = nf & 1;
                    mma16816(c[mi][nf], ah[mi], bhv[nb][hf], bhv[nb][2 + hf]);
                    mma16816(c[mi][nf], ah[mi], blv[nb][hf], blv[nb][2 + hf]);
                    mma16816(c[mi][nf], al[mi], bhv[nb][hf], bhv[nb][2 + hf]);
                }
            }
        }
        __syncthreads();
    }

    const int g  = n0 >> 10;
    const int j0 = n0 & 1023;
    const float* bias = g ? bh : bz;
    const int grp = lane >> 2, tg = lane & 3;

#pragma unroll
    for (int nf = 0; nf < 8; nf++) {
        int col = j0 + n_base + nf * 8 + tg * 2;
        float bv0 = bias[col], bv1 = bias[col + 1];
#pragma unroll
        for (int mi = 0; mi < 2; mi++) {
            int r0 = m0 + m_base + mi * 16 + grp;
            int b0i = r0 >> 9, t0 = r0 & 511;
            *(float2*)&g_X[g][t0][b0i * HIDDEN + col] =
                make_float2(c[mi][nf][0] + bv0, c[mi][nf][1] + bv1);
            int r1 = r0 + 8;
            int b1i = r1 >> 9, t1 = r1 & 511;
            *(float2*)&g_X[g][t1][b1i * HIDDEN + col] =
                make_float2(c[mi][nf][2] + bv0, c[mi][nf][3] + bv1);
        }
    }
}

// ---------------- Kernel 2: persistent HMMA recurrence -----------------------------
#define STRE 264
#define STRB (STRE * 2)
#define OFF_AHI 0
#define OFF_ALO (OFF_AHI + 128 * STRB)
#define OFF_BHI (OFF_ALO + 128 * STRB)
#define OFF_BLO (OFF_BHI + 64 * STRB)
#define SMEM_PERSIST (OFF_BLO + 64 * STRB)

__global__ __launch_bounds__(256, 1) void recurrent_persistent()
{
    extern __shared__ char smem[];
    const u32 sbase = smem_u32(smem);
    const int tid  = threadIdx.x;
    const int wid  = tid >> 5, lane = tid & 31;
    const int cta  = blockIdx.x;
    const int ks   = cta & 3;
    const int n0   = (cta >> 2) * 64;
    const int kbase = ks * 256;

    // resident B tiles (weights)
#pragma unroll
    for (int it = 0; it < 8; it++) {
        int idx = tid + it * 256;
        int row = idx >> 5;
        int c   = idx & 31;
        long src = (long)(n0 + row) * HIDDEN + kbase + c * 8;
        *(uint4*)(smem + OFF_BHI + row * STRB + c * 16) = *(const uint4*)&g_Wt_hi[src];
        *(uint4*)(smem + OFF_BLO + row * STRB + c * 16) = *(const uint4*)&g_Wt_lo[src];
    }
    __syncthreads();

    const int wm = wid & 3, wn = wid >> 2;
    const int m_base = wm * 32, n_base = wn * 32;
    const int grp = lane >> 2, tg = lane & 3;

    const u32 a_row = (u32)(lane & 15);
    const u32 b_row = (u32)((((lane >> 3) & 1) * 8) + (lane & 7));
    const u32 khalf = (u32)((lane >> 4) * 16);

    const u32 aHi0 = sbase + OFF_AHI + (m_base + a_row) * STRB + khalf;
    const u32 aLo0 = sbase + OFF_ALO + (m_base + a_row) * STRB + khalf;
    const u32 bHi0 = sbase + OFF_BHI + (n_base + b_row) * STRB + khalf;
    const u32 bLo0 = sbase + OFF_BLO + (n_base + b_row) * STRB + khalf;

    // --- update/reduce assignment: 8-CTA neighborhood owns h-cols [64j, +64) ---
    // j = h-col tile; ridx = 16-row slice within the tile (0..7)
    const int jt   = (cta >> 2) & 15;                  // my h-col tile
    const int ridx = (cta & 3) + 4 * (cta >> 6);       // row-slice index 0..7
    const int urow = 16 * ridx + (tid >> 4);           // 0..127
    const int ucol = 64 * jt + (tid & 15) * 4;         // h column (float4)
    const int uoff = urow * HIDDEN + ucol;             // in h / g_X arrays
    const int poff = urow * NTOT + ucol;               // z-gate partials
    const int qoff = poff + 1024;                      // h~-gate partials

    unsigned gen = 0, gen2 = 0;

    for (int t = 0; t < SEQL; t++) {
        const int par = t & 1;
        const __nv_bfloat16* hhi = g_hhi[par];
        const __nv_bfloat16* hlo = g_hlo[par];

        // ---- issue cp.async A staging: two K halves of 128 cols each ----
#pragma unroll
        for (int h = 0; h < 2; h++) {
#pragma unroll
            for (int it = 0; it < 8; it++) {
                int idx = tid + it * 256;        // 0..2047
                int row = idx >> 4;              // 0..127
                int c   = (idx & 15) + h * 16;   // 16B-chunk id along k
                long src = (long)row * HIDDEN + kbase + c * 8;
                u32 dst = sbase + OFF_AHI + row * STRB + c * 16;
                CP16(dst, (const void*)&hhi[src]);
                CP16(dst + (OFF_ALO - OFF_AHI), (const void*)&hlo[src]);
            }
            CP_COMMIT();
        }

        // prefetch for the reduce phase: g_X (DRAM) and previous h (stable all step)
        float4 zs = *(const float4*)&g_X[0][t][uoff];
        float4 hs = *(const float4*)&g_X[1][t][uoff];
        ull hp_hi = __ldcg((const ull*)&g_hhi[par][uoff]);
        ull hp_lo = __ldcg((const ull*)&g_hlo[par][uoff]);

        float c[2][4][4];
#pragma unroll
        for (int mi = 0; mi < 2; mi++)
#pragma unroll
            for (int nf = 0; nf < 4; nf++)
#pragma unroll
                for (int r = 0; r < 4; r++) c[mi][nf][r] = 0.0f;

        // ---- MMA: half 0 after wait_group 1; half 1 overlapped ----
#pragma unroll
        for (int half = 0; half < 2; half++) {
            if (half == 0) { CP_WAIT1(); }
            else           { CP_WAIT0(); }
            __syncthreads();
#pragma unroll
            for (int kk = 0; kk < 8; kk++) {
                const int k16 = half * 8 + kk;
                const u32 kb = (u32)(k16 * 32);
                u32 ah[2][4], al[2][4], bhv[2][4], blv[2][4];
#pragma unroll
                for (int mi = 0; mi < 2; mi++) {
                    ldmx4(ah[mi], aHi0 + mi * 16 * STRB + kb);
                    ldmx4(al[mi], aLo0 + mi * 16 * STRB + kb);
                }
#pragma unroll
                for (int nb = 0; nb < 2; nb++) {
                    ldmx4(bhv[nb], bHi0 + nb * 16 * STRB + kb);
                    ldmx4(blv[nb], bLo0 + nb * 16 * STRB + kb);
                }
#pragma unroll
                for (int mi = 0; mi < 2; mi++) {
#pragma unroll
                    for (int nf = 0; nf < 4; nf++) {
                        int nb = nf >> 1, hf = nf & 1;
                        mma16816(c[mi][nf], ah[mi], bhv[nb][hf], bhv[nb][2 + hf]);
                        mma16816(c[mi][nf], ah[mi], blv[nb][hf], blv[nb][2 + hf]);
                        mma16816(c[mi][nf], al[mi], bhv[nb][hf], bhv[nb][2 + hf]);
                    }
                }
            }
        }

        // ---- epilogue: partials -> g_P (L1-bypass) ----
#pragma unroll
        for (int mi = 0; mi < 2; mi++) {
#pragma unroll
            for (int nf = 0; nf < 4; nf++) {
                int row = m_base + mi * 16 + grp;
                int col = n0 + n_base + nf * 8 + tg * 2;
                __stcg((float2*)&g_P[ks][row * NTOT + col],
                       make_float2(c[mi][nf][0], c[mi][nf][1]));
                __stcg((float2*)&g_P[ks][(row + 8) * NTOT + col],
                       make_float2(c[mi][nf][2], c[mi][nf][3]));
            }
        }

        // barrier 1: only the 8 CTAs writing my partial tiles must arrive
        nb_barrier(cta, jt, ++gen2);

        // ---- reduce + gate + update: one float4 per thread, fully coalesced ----
        {
#pragma unroll
            for (int s = 0; s < KSPLIT; s++) {
                float4 pz = __ldcg((const float4*)&g_P[s][poff]);
                float4 ph = __ldcg((const float4*)&g_P[s][qoff]);
                zs.x += pz.x; zs.y += pz.y; zs.z += pz.z; zs.w += pz.w;
                hs.x += ph.x; hs.y += ph.y; hs.z += ph.z; hs.w += ph.w;
            }
            float hpf[4];
#pragma unroll
            for (int i = 0; i < 4; i++) {
                __nv_bfloat16 a = __ushort_as_bfloat16((unsigned short)(hp_hi >> (16 * i)));
                __nv_bfloat16 b = __ushort_as_bfloat16((unsigned short)(hp_lo >> (16 * i)));
                hpf[i] = __bfloat162float(a) + __bfloat162float(b);
            }
            float zv[4] = {zs.x, zs.y, zs.z, zs.w};
            float hv[4] = {hs.x, hs.y, hs.z, hs.w};
            unsigned short hiu[4], lou[4];
#pragma unroll
            for (int i = 0; i < 4; i++) {
                float z  = 1.0f / (1.0f + __expf(-zv[i]));
                float hn = hpf[i] + z * (tanhf(hv[i]) - hpf[i]);
                __nv_bfloat16 hb = __float2bfloat16_rn(hn);
                __nv_bfloat16 lb = __float2bfloat16_rn(hn - __bfloat162float(hb));
                hiu[i] = __bfloat16_as_ushort(hb);
                lou[i] = __bfloat16_as_ushort(lb);
            }
            ull hpack = (ull)hiu[0] | ((ull)hiu[1] << 16) | ((ull)hiu[2] << 32) | ((ull)hiu[3] << 48);
            ull lpack = (ull)lou[0] | ((ull)lou[1] << 16) | ((ull)lou[2] << 32) | ((ull)lou[3] << 48);
            __stcg((ull*)&g_hhi[par ^ 1][uoff], hpack);
            __stcg((ull*)&g_hlo[par ^ 1][uoff], lpack);
        }

        // barrier 2: everyone consumes h next step -> full sync (absorbs skew once)
        full_barrier(cta, ++gen);
    }
}

// ---------------- Kernel 3: final FC -------------------------------------------------
__global__ __launch_bounds__(128) void fc_kernel(
    const float* __restrict__ Wfc,
    const float* __restrict__ bfc,
    float* __restrict__ out)
{
    extern __shared__ float hsm[];
    const int b0 = blockIdx.y * 16;
    const int tid = threadIdx.x;

    for (int i = tid; i < 16 * HIDDEN / 4; i += 128) {
        ull hi4 = *(const ull*)&g_hhi[0][b0 * HIDDEN + i * 4];
        ull lo4 = *(const ull*)&g_hlo[0][b0 * HIDDEN + i * 4];
        float4 v;
        float* vp = (float*)&v;
#pragma unroll
        for (int j = 0; j < 4; j++) {
            __nv_bfloat16 a = __ushort_as_bfloat16((unsigned short)(hi4 >> (16 * j)));
            __nv_bfloat16 b = __ushort_as_bfloat16((unsigned short)(lo4 >> (16 * j)));
            vp[j] = __bfloat162float(a) + __bfloat162float(b);
        }
        ((float4*)hsm)[i] = v;
    }
    __syncthreads();

    const int n = blockIdx.x * 128 + tid;
    if (n >= NCLS) return;

    float acc[16];
#pragma unroll
    for (int i = 0; i < 16; i++) acc[i] = 0.0f;

    for (int k = 0; k < HIDDEN; k += 4) {
        float w0 = Wfc[(long)(k + 0) * NCLS + n];
        float w1 = Wfc[(long)(k + 1) * NCLS + n];
        float w2 = Wfc[(long)(k + 2) * NCLS + n];
        float w3 = Wfc[(long)(k + 3) * NCLS + n];
#pragma unroll
        for (int i = 0; i < 16; i++) {
            float4 h4 = *(const float4*)&hsm[i * HIDDEN + k];
            acc[i] += w0 * h4.x + w1 * h4.y + w2 * h4.z + w3 * h4.w;
        }
    }
    float bv = bfc[n];
#pragma unroll
    for (int i = 0; i < 16; i++)
        out[(long)(b0 + i) * NCLS + n] = acc[i] + bv;
}

// ---------------- launch ---------------------------------------------------------------
extern "C" void kernel_launch(void* const* d_in, const int* in_sizes, int n_in,
                              void* d_out, int out_size)
{
    const int*   x   = (const int*)d_in[0];
    const float* emb = (const float*)d_in[1];
    const float* Wz  = (const float*)d_in[2];
    const float* bz  = (const float*)d_in[3];
    const float* Wh  = (const float*)d_in[4];
    const float* bh  = (const float*)d_in[5];
    const float* Wfc = (const float*)d_in[6];
    const float* bfc = (const float*)d_in[7];
    float* out = (float*)d_out;

    cudaFuncSetAttribute(gemm_embed_mma,
                         cudaFuncAttributeMaxDynamicSharedMemorySize, SMEM_EMBED);
    cudaFuncSetAttribute(recurrent_persistent,
                         cudaFuncAttributeMaxDynamicSharedMemorySize, SMEM_PERSIST);
    cudaFuncSetAttribute(fc_kernel,
                         cudaFuncAttributeMaxDynamicSharedMemorySize, 16 * HIDDEN * 4);

    init_kernel<<<512, 256>>>();
    conv_emb<<<16000, 256>>>(emb);
    prep_weights<<<dim3(32, 64), dim3(32, 8)>>>(Wz, Wh);
    prep_win<<<dim3(16, 64), dim3(32, 8)>>>(Wz, Wh);
    gemm_embed_mma<<<dim3(16, 512), 256, SMEM_EMBED>>>(x, bz, bh);
    recurrent_persistent<<<NCTA, 256, SMEM_PERSIST>>>();
    fc_kernel<<<dim3(8, 8), 128, 16 * HIDDEN * 4>>>(Wfc, bfc, out);
}

// round 12
// speedup vs baseline: 1.1053x; 1.1053x over previous
#include <cuda_runtime.h>
#include <cuda_bf16.h>
#include <math.h>
#include <stdint.h>

#define BATCH  128
#define SEQL   512
#define EMBED  512
#define HIDDEN 1024
#define NCLS   1000
#define NTOT   2048

#define NCTA   128            // worker CTAs; CTA 128 is the barrier master
#define KSPLIT 4

typedef unsigned long long ull;
typedef unsigned int u32;

// ---------------- device scratch -----------------------------------------------
__device__ float g_X[2][SEQL][BATCH * HIDDEN];     // x_t @ W_in + b, per gate
__device__ float g_P[KSPLIT][BATCH * NTOT];        // k-split partials
__device__ __nv_bfloat16 g_hhi[2][BATCH * HIDDEN]; // h state, bf16 hi (ping-pong)
__device__ __nv_bfloat16 g_hlo[2][BATCH * HIDDEN]; // h state, bf16 lo
__device__ __nv_bfloat16 g_Wt_hi[NTOT * HIDDEN];   // recurrent W^T hi  [n][k]
__device__ __nv_bfloat16 g_Wt_lo[NTOT * HIDDEN];
__device__ __nv_bfloat16 g_Win_hi[NTOT * EMBED];   // input-proj W^T hi [n][k]
__device__ __nv_bfloat16 g_Win_lo[NTOT * EMBED];
__device__ __nv_bfloat16 g_emb_hi[32000 * EMBED];  // emb table bf16 hi
__device__ __nv_bfloat16 g_emb_lo[32000 * EMBED];

__device__ unsigned g_flags[NCTA];     // barrier arrive flags
__device__ unsigned g_release;         // barrier release word (master-written)

// ---------------- MMA / ldmatrix / cp.async helpers ----------------------------
__device__ __forceinline__ u32 smem_u32(const void* p) {
    u32 a;
    asm("{ .reg .u64 t; cvta.to.shared.u64 t, %1; cvt.u32.u64 %0, t; }" : "=r"(a) : "l"(p));
    return a;
}
__device__ __forceinline__ void ldmx4(u32* r, u32 addr) {
    asm volatile("ldmatrix.sync.aligned.m8n8.x4.shared.b16 {%0,%1,%2,%3}, [%4];"
                 : "=r"(r[0]), "=r"(r[1]), "=r"(r[2]), "=r"(r[3]) : "r"(addr));
}
__device__ __forceinline__ void mma16816(float* c, const u32* a, u32 b0, u32 b1) {
    asm volatile("mma.sync.aligned.m16n8k16.row.col.f32.bf16.bf16.f32 "
                 "{%0,%1,%2,%3}, {%4,%5,%6,%7}, {%8,%9}, {%0,%1,%2,%3};"
                 : "+f"(c[0]), "+f"(c[1]), "+f"(c[2]), "+f"(c[3])
                 : "r"(a[0]), "r"(a[1]), "r"(a[2]), "r"(a[3]), "r"(b0), "r"(b1));
}
#define CP16(dst, src) \
    asm volatile("cp.async.cg.shared.global [%0], [%1], 16;" :: "r"(dst), "l"(src) : "memory")
#define CP_COMMIT() asm volatile("cp.async.commit_group;" ::: "memory")
#define CP_WAIT1()  asm volatile("cp.async.wait_group 1;" ::: "memory")
#define CP_WAIT0()  asm volatile("cp.async.wait_group 0;" ::: "memory")

// ---------------- worker-side barrier: arrive flag, wait on master release ------
__device__ __forceinline__ void full_barrier(int cta, unsigned gen) {
    __syncthreads();
    if (threadIdx.x == 0) {
        __threadfence();                                   // release my CTA's stores
        *((volatile unsigned*)&g_flags[cta]) = gen;
        while (*((volatile unsigned*)&g_release) < gen) { }
        __threadfence();                                   // acquire
    }
    __syncthreads();
}

// ---------------- init ------------------------------------------------------------
__global__ void init_kernel() {
    int i = blockIdx.x * 256 + threadIdx.x;           // 0..131071
    __nv_bfloat16 z = __float2bfloat16(0.0f);
    g_hhi[0][i] = z; g_hhi[1][i] = z;
    g_hlo[0][i] = z; g_hlo[1][i] = z;
    if (i < NCTA) g_flags[i] = 0;
    if (i == 0) g_release = 0;
}

// ---------------- emb table -> bf16 hi/lo ------------------------------------------
__global__ void conv_emb(const float* __restrict__ emb) {
    long i = (long)blockIdx.x * 256 + threadIdx.x;
    float4 v = *(const float4*)&emb[i * 4];
    float f[4] = {v.x, v.y, v.z, v.w};
    unsigned short hiu[4], lou[4];
#pragma unroll
    for (int j = 0; j < 4; j++) {
        __nv_bfloat16 hb = __float2bfloat16_rn(f[j]);
        __nv_bfloat16 lb = __float2bfloat16_rn(f[j] - __bfloat162float(hb));
        hiu[j] = __bfloat16_as_ushort(hb);
        lou[j] = __bfloat16_as_ushort(lb);
    }
    *(ull*)&g_emb_hi[i * 4] = (ull)hiu[0] | ((ull)hiu[1] << 16) | ((ull)hiu[2] << 32) | ((ull)hiu[3] << 48);
    *(ull*)&g_emb_lo[i * 4] = (ull)lou[0] | ((ull)lou[1] << 16) | ((ull)lou[2] << 32) | ((ull)lou[3] << 48);
}

// ---------------- weight prep: recurrent part (k in [512,1536)) --------------------
__global__ void prep_weights(const float* __restrict__ Wz,
                             const float* __restrict__ Wh)
{
    __shared__ float tile[32][33];
    const int k0  = blockIdx.x * 32;
    const int n0g = blockIdx.y * 32;
    const float* W = (n0g < 1024) ? Wz : Wh;
    const int nc0 = n0g & 1023;

    for (int r = threadIdx.y; r < 32; r += 8)
        tile[r][threadIdx.x] = W[(long)(512 + k0 + r) * HIDDEN + nc0 + threadIdx.x];
    __syncthreads();
    for (int r2 = threadIdx.y; r2 < 32; r2 += 8) {
        float v = tile[threadIdx.x][r2];
        __nv_bfloat16 hi = __float2bfloat16_rn(v);
        __nv_bfloat16 lo = __float2bfloat16_rn(v - __bfloat162float(hi));
        long o = (long)(n0g + r2) * HIDDEN + k0 + threadIdx.x;
        g_Wt_hi[o] = hi;
        g_Wt_lo[o] = lo;
    }
}

// ---------------- weight prep: input part (k in [0,512)) ---------------------------
__global__ void prep_win(const float* __restrict__ Wz,
                         const float* __restrict__ Wh)
{
    __shared__ float tile[32][33];
    const int k0  = blockIdx.x * 32;
    const int n0g = blockIdx.y * 32;
    const float* W = (n0g < 1024) ? Wz : Wh;
    const int nc0 = n0g & 1023;

    for (int r = threadIdx.y; r < 32; r += 8)
        tile[r][threadIdx.x] = W[(long)(k0 + r) * HIDDEN + nc0 + threadIdx.x];
    __syncthreads();
    for (int r2 = threadIdx.y; r2 < 32; r2 += 8) {
        float v = tile[threadIdx.x][r2];
        __nv_bfloat16 hi = __float2bfloat16_rn(v);
        __nv_bfloat16 lo = __float2bfloat16_rn(v - __bfloat162float(hi));
        long o = (long)(n0g + r2) * EMBED + k0 + threadIdx.x;
        g_Win_hi[o] = hi;
        g_Win_lo[o] = lo;
    }
}

// ---------------- Kernel 1: HMMA embedding projection ------------------------------
#define E_STRB 144
#define E_MAT  18432
#define E_BUF  (4 * E_MAT)
#define E_SIDX (2 * E_BUF)
#define SMEM_EMBED (E_SIDX + 512)

__global__ __launch_bounds__(256, 1) void gemm_embed_mma(
    const int*   __restrict__ x,
    const float* __restrict__ bz,
    const float* __restrict__ bh)
{
    extern __shared__ char smem[];
    const u32 sbase = smem_u32(smem);
    const int tid = threadIdx.x;
    const int wid = tid >> 5, lane = tid & 31;
    const int n0 = blockIdx.x * 128;
    const int m0 = blockIdx.y * 128;

    int* sidx = (int*)(smem + E_SIDX);
    if (tid < 128) sidx[tid] = x[m0 + tid];
    __syncthreads();

    const int srow[4] = { (tid + 0)   >> 3, (tid + 256) >> 3,
                          (tid + 512) >> 3, (tid + 768) >> 3 };
    const int sc = tid & 7;

    auto issue_tile = [&](int kt, int b) {
        const int k0 = kt * 64;
#pragma unroll
        for (int j = 0; j < 4; j++) {
            int row = srow[j];
            u32 dst = sbase + b * E_BUF + row * E_STRB + sc * 16;
            long aoff = (long)sidx[row] * EMBED + k0 + sc * 8;
            long boff = (long)(n0 + row) * EMBED + k0 + sc * 8;
            CP16(dst,             (const void*)&g_emb_hi[aoff]);
            CP16(dst + E_MAT,     (const void*)&g_emb_lo[aoff]);
            CP16(dst + 2 * E_MAT, (const void*)&g_Win_hi[boff]);
            CP16(dst + 3 * E_MAT, (const void*)&g_Win_lo[boff]);
        }
        CP_COMMIT();
    };

    const int m_base = (wid & 3) * 32;
    const int n_base = (wid >> 2) * 64;
    const u32 a_row = (u32)(lane & 15);
    const u32 b_row = (u32)((((lane >> 3) & 1) * 8) + (lane & 7));
    const u32 khalf = (u32)((lane >> 4) * 16);

    float c[2][8][4];
#pragma unroll
    for (int mi = 0; mi < 2; mi++)
#pragma unroll
        for (int nf = 0; nf < 8; nf++)
#pragma unroll
            for (int r = 0; r < 4; r++) c[mi][nf][r] = 0.0f;

    issue_tile(0, 0);

    for (int kt = 0; kt < 8; kt++) {
        if (kt < 7) { issue_tile(kt + 1, (kt + 1) & 1); CP_WAIT1(); }
        else        { CP_WAIT0(); }
        __syncthreads();

        const u32 base = sbase + (kt & 1) * E_BUF;
#pragma unroll
        for (int k16 = 0; k16 < 4; k16++) {
            const u32 kb = (u32)(k16 * 32) + khalf;
            u32 ah[2][4], al[2][4], bhv[4][4], blv[4][4];
#pragma unroll
            for (int mi = 0; mi < 2; mi++) {
                u32 ar = base + (m_base + mi * 16 + a_row) * E_STRB + kb;
                ldmx4(ah[mi], ar);
                ldmx4(al[mi], ar + E_MAT);
            }
#pragma unroll
            for (int nb = 0; nb < 4; nb++) {
                u32 br = base + 2 * E_MAT + (n_base + nb * 16 + b_row) * E_STRB + kb;
                ldmx4(bhv[nb], br);
                ldmx4(blv[nb], br + E_MAT);
            }
#pragma unroll
            for (int mi = 0; mi < 2; mi++) {
#pragma unroll
                for (int nf = 0; nf < 8; nf++) {
                    int nb = nf >> 1, hf = nf & 1;
                    mma16816(c[mi][nf], ah[mi], bhv[nb][hf], bhv[nb][2 + hf]);
                    mma16816(c[mi][nf], ah[mi], blv[nb][hf], blv[nb][2 + hf]);
                    mma16816(c[mi][nf], al[mi], bhv[nb][hf], bhv[nb][2 + hf]);
                }
            }
        }
        __syncthreads();
    }

    const int g  = n0 >> 10;
    const int j0 = n0 & 1023;
    const float* bias = g ? bh : bz;
    const int grp = lane >> 2, tg = lane & 3;

#pragma unroll
    for (int nf = 0; nf < 8; nf++) {
        int col = j0 + n_base + nf * 8 + tg * 2;
        float bv0 = bias[col], bv1 = bias[col + 1];
#pragma unroll
        for (int mi = 0; mi < 2; mi++) {
            int r0 = m0 + m_base + mi * 16 + grp;
            int b0i = r0 >> 9, t0 = r0 & 511;
            *(float2*)&g_X[g][t0][b0i * HIDDEN + col] =
                make_float2(c[mi][nf][0] + bv0, c[mi][nf][1] + bv1);
            int r1 = r0 + 8;
            int b1i = r1 >> 9, t1 = r1 & 511;
            *(float2*)&g_X[g][t1][b1i * HIDDEN + col] =
                make_float2(c[mi][nf][2] + bv0, c[mi][nf][3] + bv1);
        }
    }
}

// ---------------- Kernel 2: persistent HMMA recurrence -----------------------------
#define STRE 264
#define STRB (STRE * 2)
#define OFF_AHI 0
#define OFF_ALO (OFF_AHI + 128 * STRB)
#define OFF_BHI (OFF_ALO + 128 * STRB)
#define OFF_BLO (OFF_BHI + 64 * STRB)
#define SMEM_PERSIST (OFF_BLO + 64 * STRB)

__global__ __launch_bounds__(256, 1) void recurrent_persistent()
{
    extern __shared__ char smem[];
    const u32 sbase = smem_u32(smem);
    const int tid  = threadIdx.x;
    const int cta  = blockIdx.x;

    // ---- dedicated barrier master: CTA 128 -------------------------------------
    if (cta == NCTA) {
        for (unsigned g = 1; g <= 2u * SEQL; g++) {
            if (tid < NCTA) {
                while (*((volatile unsigned*)&g_flags[tid]) < g) { }
            }
            __syncthreads();
            if (tid == 0) {
                __threadfence();                       // order flag-acquire -> release
                *((volatile unsigned*)&g_release) = g;
            }
            __syncthreads();
        }
        return;
    }

    const int wid  = tid >> 5, lane = tid & 31;
    const int ks   = cta & 3;
    const int n0   = (cta >> 2) * 64;
    const int kbase = ks * 256;

    // resident B tiles (weights)
#pragma unroll
    for (int it = 0; it < 8; it++) {
        int idx = tid + it * 256;
        int row = idx >> 5;
        int c   = idx & 31;
        long src = (long)(n0 + row) * HIDDEN + kbase + c * 8;
        *(uint4*)(smem + OFF_BHI + row * STRB + c * 16) = *(const uint4*)&g_Wt_hi[src];
        *(uint4*)(smem + OFF_BLO + row * STRB + c * 16) = *(const uint4*)&g_Wt_lo[src];
    }
    __syncthreads();

    const int wm = wid & 3, wn = wid >> 2;
    const int m_base = wm * 32, n_base = wn * 32;
    const int grp = lane >> 2, tg = lane & 3;

    const u32 a_row = (u32)(lane & 15);
    const u32 b_row = (u32)((((lane >> 3) & 1) * 8) + (lane & 7));
    const u32 khalf = (u32)((lane >> 4) * 16);

    const u32 aHi0 = sbase + OFF_AHI + (m_base + a_row) * STRB + khalf;
    const u32 aLo0 = sbase + OFF_ALO + (m_base + a_row) * STRB + khalf;
    const u32 bHi0 = sbase + OFF_BHI + (n_base + b_row) * STRB + khalf;
    const u32 bLo0 = sbase + OFF_BLO + (n_base + b_row) * STRB + khalf;

    // reduce-phase assignment: 4 consecutive h elements per thread (row-contiguous)
    const int ubase = (cta * 256 + tid) * 4;
    const int um = ubase >> 10;
    const int uj = ubase & 1023;

    unsigned gen = 0;

    for (int t = 0; t < SEQL; t++) {
        const int par = t & 1;
        const __nv_bfloat16* hhi = g_hhi[par];
        const __nv_bfloat16* hlo = g_hlo[par];

        // ---- issue cp.async A staging: two K halves of 128 cols each ----
#pragma unroll
        for (int h = 0; h < 2; h++) {
#pragma unroll
            for (int it = 0; it < 8; it++) {
                int idx = tid + it * 256;        // 0..2047
                int row = idx >> 4;              // 0..127
                int c   = (idx & 15) + h * 16;   // 16B-chunk id along k
                long src = (long)row * HIDDEN + kbase + c * 8;
                u32 dst = sbase + OFF_AHI + row * STRB + c * 16;
                CP16(dst, (const void*)&hhi[src]);
                CP16(dst + (OFF_ALO - OFF_AHI), (const void*)&hlo[src]);
            }
            CP_COMMIT();
        }

        // prefetch this step's input-projection values (DRAM) for the reduce phase
        float4 zs = *(const float4*)&g_X[0][t][um * HIDDEN + uj];
        float4 hs = *(const float4*)&g_X[1][t][um * HIDDEN + uj];

        float c[2][4][4];
#pragma unroll
        for (int mi = 0; mi < 2; mi++)
#pragma unroll
            for (int nf = 0; nf < 4; nf++)
#pragma unroll
                for (int r = 0; r < 4; r++) c[mi][nf][r] = 0.0f;

        // ---- MMA: half 0 after wait_group 1; half 1 overlapped ----
#pragma unroll
        for (int half = 0; half < 2; half++) {
            if (half == 0) { CP_WAIT1(); }
            else           { CP_WAIT0(); }
            __syncthreads();
#pragma unroll
            for (int kk = 0; kk < 8; kk++) {
                const int k16 = half * 8 + kk;
                const u32 kb = (u32)(k16 * 32);
                u32 ah[2][4], al[2][4], bhv[2][4], blv[2][4];
#pragma unroll
                for (int mi = 0; mi < 2; mi++) {
                    ldmx4(ah[mi], aHi0 + mi * 16 * STRB + kb);
                    ldmx4(al[mi], aLo0 + mi * 16 * STRB + kb);
                }
#pragma unroll
                for (int nb = 0; nb < 2; nb++) {
                    ldmx4(bhv[nb], bHi0 + nb * 16 * STRB + kb);
                    ldmx4(blv[nb], bLo0 + nb * 16 * STRB + kb);
                }
#pragma unroll
                for (int mi = 0; mi < 2; mi++) {
#pragma unroll
                    for (int nf = 0; nf < 4; nf++) {
                        int nb = nf >> 1, hf = nf & 1;
                        mma16816(c[mi][nf], ah[mi], bhv[nb][hf], bhv[nb][2 + hf]);
                        mma16816(c[mi][nf], ah[mi], blv[nb][hf], blv[nb][2 + hf]);
                        mma16816(c[mi][nf], al[mi], bhv[nb][hf], bhv[nb][2 + hf]);
                    }
                }
            }
        }

        // ---- epilogue: partials -> g_P (L1-bypass) ----
#pragma unroll
        for (int mi = 0; mi < 2; mi++) {
#pragma unroll
            for (int nf = 0; nf < 4; nf++) {
                int row = m_base + mi * 16 + grp;
                int col = n0 + n_base + nf * 8 + tg * 2;
                __stcg((float2*)&g_P[ks][row * NTOT + col],
                       make_float2(c[mi][nf][0], c[mi][nf][1]));
                __stcg((float2*)&g_P[ks][(row + 8) * NTOT + col],
                       make_float2(c[mi][nf][2], c[mi][nf][3]));
            }
        }

        full_barrier(cta, ++gen);

        // ---- reduce + gate + update: one float4 per thread, fully coalesced ----
        {
#pragma unroll
            for (int s = 0; s < KSPLIT; s++) {
                float4 pz = __ldcg((const float4*)&g_P[s][um * NTOT + uj]);
                float4 ph = __ldcg((const float4*)&g_P[s][um * NTOT + 1024 + uj]);
                zs.x += pz.x; zs.y += pz.y; zs.z += pz.z; zs.w += pz.w;
                hs.x += ph.x; hs.y += ph.y; hs.z += ph.z; hs.w += ph.w;
            }
            ull hp_hi = __ldcg((const ull*)&g_hhi[par][um * HIDDEN + uj]);
            ull hp_lo = __ldcg((const ull*)&g_hlo[par][um * HIDDEN + uj]);
            float hpf[4];
#pragma unroll
            for (int i = 0; i < 4; i++) {
                __nv_bfloat16 a = __ushort_as_bfloat16((unsigned short)(hp_hi >> (16 * i)));
                __nv_bfloat16 b = __ushort_as_bfloat16((unsigned short)(hp_lo >> (16 * i)));
                hpf[i] = __bfloat162float(a) + __bfloat162float(b);
            }
            float zv[4] = {zs.x, zs.y, zs.z, zs.w};
            float hv[4] = {hs.x, hs.y, hs.z, hs.w};
            unsigned short hiu[4], lou[4];
#pragma unroll
            for (int i = 0; i < 4; i++) {
                float z  = 1.0f / (1.0f + __expf(-zv[i]));
                float hn = hpf[i] + z * (tanhf(hv[i]) - hpf[i]);
                __nv_bfloat16 hb = __float2bfloat16_rn(hn);
                __nv_bfloat16 lb = __float2bfloat16_rn(hn - __bfloat162float(hb));
                hiu[i] = __bfloat16_as_ushort(hb);
                lou[i] = __bfloat16_as_ushort(lb);
            }
            ull hpack = (ull)hiu[0] | ((ull)hiu[1] << 16) | ((ull)hiu[2] << 32) | ((ull)hiu[3] << 48);
            ull lpack = (ull)lou[0] | ((ull)lou[1] << 16) | ((ull)lou[2] << 32) | ((ull)lou[3] << 48);
            __stcg((ull*)&g_hhi[par ^ 1][um * HIDDEN + uj], hpack);
            __stcg((ull*)&g_hlo[par ^ 1][um * HIDDEN + uj], lpack);
        }

        full_barrier(cta, ++gen);
    }
}

// ---------------- Kernel 3: final FC -------------------------------------------------
__global__ __launch_bounds__(128) void fc_kernel(
    const float* __restrict__ Wfc,
    const float* __restrict__ bfc,
    float* __restrict__ out)
{
    extern __shared__ float hsm[];
    const int b0 = blockIdx.y * 16;
    const int tid = threadIdx.x;

    for (int i = tid; i < 16 * HIDDEN / 4; i += 128) {
        ull hi4 = *(const ull*)&g_hhi[0][b0 * HIDDEN + i * 4];
        ull lo4 = *(const ull*)&g_hlo[0][b0 * HIDDEN + i * 4];
        float4 v;
        float* vp = (float*)&v;
#pragma unroll
        for (int j = 0; j < 4; j++) {
            __nv_bfloat16 a = __ushort_as_bfloat16((unsigned short)(hi4 >> (16 * j)));
            __nv_bfloat16 b = __ushort_as_bfloat16((unsigned short)(lo4 >> (16 * j)));
            vp[j] = __bfloat162float(a) + __bfloat162float(b);
        }
        ((float4*)hsm)[i] = v;
    }
    __syncthreads();

    const int n = blockIdx.x * 128 + tid;
    if (n >= NCLS) return;

    float acc[16];
#pragma unroll
    for (int i = 0; i < 16; i++) acc[i] = 0.0f;

    for (int k = 0; k < HIDDEN; k += 4) {
        float w0 = Wfc[(long)(k + 0) * NCLS + n];
        float w1 = Wfc[(long)(k + 1) * NCLS + n];
        float w2 = Wfc[(long)(k + 2) * NCLS + n];
        float w3 = Wfc[(long)(k + 3) * NCLS + n];
#pragma unroll
        for (int i = 0; i < 16; i++) {
            float4 h4 = *(const float4*)&hsm[i * HIDDEN + k];
            acc[i] += w0 * h4.x + w1 * h4.y + w2 * h4.z + w3 * h4.w;
        }
    }
    float bv = bfc[n];
#pragma unroll
    for (int i = 0; i < 16; i++)
        out[(long)(b0 + i) * NCLS + n] = acc[i] + bv;
}

// ---------------- launch ---------------------------------------------------------------
extern "C" void kernel_launch(void* const* d_in, const int* in_sizes, int n_in,
                              void* d_out, int out_size)
{
    const int*   x   = (const int*)d_in[0];
    const float* emb = (const float*)d_in[1];
    const float* Wz  = (const float*)d_in[2];
    const float* bz  = (const float*)d_in[3];
    const float* Wh  = (const float*)d_in[4];
    const float* bh  = (const float*)d_in[5];
    const float* Wfc = (const float*)d_in[6];
    const float* bfc = (const float*)d_in[7];
    float* out = (float*)d_out;

    cudaFuncSetAttribute(gemm_embed_mma,
                         cudaFuncAttributeMaxDynamicSharedMemorySize, SMEM_EMBED);
    cudaFuncSetAttribute(recurrent_persistent,
                         cudaFuncAttributeMaxDynamicSharedMemorySize, SMEM_PERSIST);
    cudaFuncSetAttribute(fc_kernel,
                         cudaFuncAttributeMaxDynamicSharedMemorySize, 16 * HIDDEN * 4);

    init_kernel<<<512, 256>>>();
    conv_emb<<<16000, 256>>>(emb);
    prep_weights<<<dim3(32, 64), dim3(32, 8)>>>(Wz, Wh);
    prep_win<<<dim3(16, 64), dim3(32, 8)>>>(Wz, Wh);
    gemm_embed_mma<<<dim3(16, 512), 256, SMEM_EMBED>>>(x, bz, bh);
    recurrent_persistent<<<NCTA + 1, 256, SMEM_PERSIST>>>();
    fc_kernel<<<dim3(8, 8), 128, 16 * HIDDEN * 4>>>(Wfc, bfc, out);
}

// round 13
// speedup vs baseline: 1.1779x; 1.0657x over previous
#include <cuda_runtime.h>
#include <cuda_bf16.h>
#include <math.h>
#include <stdint.h>

#define BATCH  128
#define SEQL   512
#define EMBED  512
#define HIDDEN 1024
#define NCLS   1000
#define NTOT   2048

#define NCTA   128
#define KSPLIT 4

typedef unsigned long long ull;
typedef unsigned int u32;

// ---------------- device scratch -----------------------------------------------
__device__ float g_X[2][SEQL][BATCH * HIDDEN];     // x_t @ W_in + b, per gate
__device__ float g_P[KSPLIT][BATCH * NTOT];        // k-split partials
__device__ __nv_bfloat16 g_hhi[2][BATCH * HIDDEN]; // h state, bf16 hi (ping-pong)
__device__ __nv_bfloat16 g_hlo[2][BATCH * HIDDEN]; // h state, bf16 lo
__device__ __nv_bfloat16 g_Wt_hi[NTOT * HIDDEN];   // recurrent W^T hi  [n][k]
__device__ __nv_bfloat16 g_Wt_lo[NTOT * HIDDEN];
__device__ __nv_bfloat16 g_Win_hi[NTOT * EMBED];   // input-proj W^T hi [n][k]
__device__ __nv_bfloat16 g_Win_lo[NTOT * EMBED];
__device__ __nv_bfloat16 g_emb_hi[32000 * EMBED];  // emb table bf16 hi
__device__ __nv_bfloat16 g_emb_lo[32000 * EMBED];

__device__ unsigned g_flags[NCTA];     // full barrier arrive flags
__device__ unsigned g_release;         // full barrier release word

// ---------------- MMA / ldmatrix / cp.async helpers ----------------------------
__device__ __forceinline__ u32 smem_u32(const void* p) {
    u32 a;
    asm("{ .reg .u64 t; cvta.to.shared.u64 t, %1; cvt.u32.u64 %0, t; }" : "=r"(a) : "l"(p));
    return a;
}
__device__ __forceinline__ void ldmx4(u32* r, u32 addr) {
    asm volatile("ldmatrix.sync.aligned.m8n8.x4.shared.b16 {%0,%1,%2,%3}, [%4];"
                 : "=r"(r[0]), "=r"(r[1]), "=r"(r[2]), "=r"(r[3]) : "r"(addr));
}
__device__ __forceinline__ void mma16816(float* c, const u32* a, u32 b0, u32 b1) {
    asm volatile("mma.sync.aligned.m16n8k16.row.col.f32.bf16.bf16.f32 "
                 "{%0,%1,%2,%3}, {%4,%5,%6,%7}, {%8,%9}, {%0,%1,%2,%3};"
                 : "+f"(c[0]), "+f"(c[1]), "+f"(c[2]), "+f"(c[3])
                 : "r"(a[0]), "r"(a[1]), "r"(a[2]), "r"(a[3]), "r"(b0), "r"(b1));
}
#define CP16(dst, src) \
    asm volatile("cp.async.cg.shared.global [%0], [%1], 16;" :: "r"(dst), "l"(src) : "memory")
#define CP_COMMIT() asm volatile("cp.async.commit_group;" ::: "memory")
#define CP_WAIT1()  asm volatile("cp.async.wait_group 1;" ::: "memory")
#define CP_WAIT0()  asm volatile("cp.async.wait_group 0;" ::: "memory")

// ---------------- full barrier (two-stage: flags -> CTA0 -> release) ------------
__device__ __forceinline__ void full_barrier(int cta, unsigned gen) {
    __syncthreads();
    if (threadIdx.x == 0) {
        __threadfence();
        *((volatile unsigned*)&g_flags[cta]) = gen;
    }
    if (cta == 0) {
        if (threadIdx.x < NCTA) {
            while (*((volatile unsigned*)&g_flags[threadIdx.x]) < gen) { }
        }
        __syncthreads();
        if (threadIdx.x == 0) {
            __threadfence();
            *((volatile unsigned*)&g_release) = gen;
        }
    }
    if (threadIdx.x == 0) {
        while (*((volatile unsigned*)&g_release) < gen) { }
        __threadfence();
    }
    __syncthreads();
}

// ---------------- init ------------------------------------------------------------
__global__ void init_kernel() {
    int i = blockIdx.x * 256 + threadIdx.x;           // 0..131071
    __nv_bfloat16 z = __float2bfloat16(0.0f);
    g_hhi[0][i] = z; g_hhi[1][i] = z;
    g_hlo[0][i] = z; g_hlo[1][i] = z;
    if (i < NCTA) g_flags[i] = 0;
    if (i == 0) g_release = 0;
}

// ---------------- emb table -> bf16 hi/lo ------------------------------------------
__global__ void conv_emb(const float* __restrict__ emb) {
    long i = (long)blockIdx.x * 256 + threadIdx.x;
    float4 v = *(const float4*)&emb[i * 4];
    float f[4] = {v.x, v.y, v.z, v.w};
    unsigned short hiu[4], lou[4];
#pragma unroll
    for (int j = 0; j < 4; j++) {
        __nv_bfloat16 hb = __float2bfloat16_rn(f[j]);
        __nv_bfloat16 lb = __float2bfloat16_rn(f[j] - __bfloat162float(hb));
        hiu[j] = __bfloat16_as_ushort(hb);
        lou[j] = __bfloat16_as_ushort(lb);
    }
    *(ull*)&g_emb_hi[i * 4] = (ull)hiu[0] | ((ull)hiu[1] << 16) | ((ull)hiu[2] << 32) | ((ull)hiu[3] << 48);
    *(ull*)&g_emb_lo[i * 4] = (ull)lou[0] | ((ull)lou[1] << 16) | ((ull)lou[2] << 32) | ((ull)lou[3] << 48);
}

// ---------------- weight prep: recurrent part (k in [512,1536)) --------------------
__global__ void prep_weights(const float* __restrict__ Wz,
                             const float* __restrict__ Wh)
{
    __shared__ float tile[32][33];
    const int k0  = blockIdx.x * 32;
    const int n0g = blockIdx.y * 32;
    const float* W = (n0g < 1024) ? Wz : Wh;
    const int nc0 = n0g & 1023;

    for (int r = threadIdx.y; r < 32; r += 8)
        tile[r][threadIdx.x] = W[(long)(512 + k0 + r) * HIDDEN + nc0 + threadIdx.x];
    __syncthreads();
    for (int r2 = threadIdx.y; r2 < 32; r2 += 8) {
        float v = tile[threadIdx.x][r2];
        __nv_bfloat16 hi = __float2bfloat16_rn(v);
        __nv_bfloat16 lo = __float2bfloat16_rn(v - __bfloat162float(hi));
        long o = (long)(n0g + r2) * HIDDEN + k0 + threadIdx.x;
        g_Wt_hi[o] = hi;
        g_Wt_lo[o] = lo;
    }
}

// ---------------- weight prep: input part (k in [0,512)) ---------------------------
__global__ void prep_win(const float* __restrict__ Wz,
                         const float* __restrict__ Wh)
{
    __shared__ float tile[32][33];
    const int k0  = blockIdx.x * 32;
    const int n0g = blockIdx.y * 32;
    const float* W = (n0g < 1024) ? Wz : Wh;
    const int nc0 = n0g & 1023;

    for (int r = threadIdx.y; r < 32; r += 8)
        tile[r][threadIdx.x] = W[(long)(k0 + r) * HIDDEN + nc0 + threadIdx.x];
    __syncthreads();
    for (int r2 = threadIdx.y; r2 < 32; r2 += 8) {
        float v = tile[threadIdx.x][r2];
        __nv_bfloat16 hi = __float2bfloat16_rn(v);
        __nv_bfloat16 lo = __float2bfloat16_rn(v - __bfloat162float(hi));
        long o = (long)(n0g + r2) * EMBED + k0 + threadIdx.x;
        g_Win_hi[o] = hi;
        g_Win_lo[o] = lo;
    }
}

// ---------------- Kernel 1: HMMA embedding projection ------------------------------
#define E_STRB 144
#define E_MAT  18432
#define E_BUF  (4 * E_MAT)
#define E_SIDX (2 * E_BUF)
#define SMEM_EMBED (E_SIDX + 512)

__global__ __launch_bounds__(256, 1) void gemm_embed_mma(
    const int*   __restrict__ x,
    const float* __restrict__ bz,
    const float* __restrict__ bh)
{
    extern __shared__ char smem[];
    const u32 sbase = smem_u32(smem);
    const int tid = threadIdx.x;
    const int wid = tid >> 5, lane = tid & 31;
    const int n0 = blockIdx.x * 128;
    const int m0 = blockIdx.y * 128;

    int* sidx = (int*)(smem + E_SIDX);
    if (tid < 128) sidx[tid] = x[m0 + tid];
    __syncthreads();

    const int srow[4] = { (tid + 0)   >> 3, (tid + 256) >> 3,
                          (tid + 512) >> 3, (tid + 768) >> 3 };
    const int sc = tid & 7;

    auto issue_tile = [&](int kt, int b) {
        const int k0 = kt * 64;
#pragma unroll
        for (int j = 0; j < 4; j++) {
            int row = srow[j];
            u32 dst = sbase + b * E_BUF + row * E_STRB + sc * 16;
            long aoff = (long)sidx[row] * EMBED + k0 + sc * 8;
            long boff = (long)(n0 + row) * EMBED + k0 + sc * 8;
            CP16(dst,             (const void*)&g_emb_hi[aoff]);
            CP16(dst + E_MAT,     (const void*)&g_emb_lo[aoff]);
            CP16(dst + 2 * E_MAT, (const void*)&g_Win_hi[boff]);
            CP16(dst + 3 * E_MAT, (const void*)&g_Win_lo[boff]);
        }
        CP_COMMIT();
    };

    const int m_base = (wid & 3) * 32;
    const int n_base = (wid >> 2) * 64;
    const u32 a_row = (u32)(lane & 15);
    const u32 b_row = (u32)((((lane >> 3) & 1) * 8) + (lane & 7));
    const u32 khalf = (u32)((lane >> 4) * 16);

    float c[2][8][4];
#pragma unroll
    for (int mi = 0; mi < 2; mi++)
#pragma unroll
        for (int nf = 0; nf < 8; nf++)
#pragma unroll
            for (int r = 0; r < 4; r++) c[mi][nf][r] = 0.0f;

    issue_tile(0, 0);

    for (int kt = 0; kt < 8; kt++) {
        if (kt < 7) { issue_tile(kt + 1, (kt + 1) & 1); CP_WAIT1(); }
        else        { CP_WAIT0(); }
        __syncthreads();

        const u32 base = sbase + (kt & 1) * E_BUF;
#pragma unroll
        for (int k16 = 0; k16 < 4; k16++) {
            const u32 kb = (u32)(k16 * 32) + khalf;
            u32 ah[2][4], al[2][4], bhv[4][4], blv[4][4];
#pragma unroll
            for (int mi = 0; mi < 2; mi++) {
                u32 ar = base + (m_base + mi * 16 + a_row) * E_STRB + kb;
                ldmx4(ah[mi], ar);
                ldmx4(al[mi], ar + E_MAT);
            }
#pragma unroll
            for (int nb = 0; nb < 4; nb++) {
                u32 br = base + 2 * E_MAT + (n_base + nb * 16 + b_row) * E_STRB + kb;
                ldmx4(bhv[nb], br);
                ldmx4(blv[nb], br + E_MAT);
            }
#pragma unroll
            for (int mi = 0; mi < 2; mi++) {
#pragma unroll
                for (int nf = 0; nf < 8; nf++) {
                    int nb = nf >> 1, hf = nf & 1;
                    mma16816(c[mi][nf], ah[mi], bhv[nb][hf], bhv[nb][2 + hf]);
                    mma16816(c[mi][nf], ah[mi], blv[nb][hf], blv[nb][2 + hf]);
                    mma16816(c[mi][nf], al[mi], bhv[nb][hf], bhv[nb][2 + hf]);
                }
            }
        }
        __syncthreads();
    }

    const int g  = n0 >> 10;
    const int j0 = n0 & 1023;
    const float* bias = g ? bh : bz;
    const int grp = lane >> 2, tg = lane & 3;

#pragma unroll
    for (int nf = 0; nf < 8; nf++) {
        int col = j0 + n_base + nf * 8 + tg * 2;
        float bv0 = bias[col], bv1 = bias[col + 1];
#pragma unroll
        for (int mi = 0; mi < 2; mi++) {
            int r0 = m0 + m_base + mi * 16 + grp;
            int b0i = r0 >> 9, t0 = r0 & 511;
            *(float2*)&g_X[g][t0][b0i * HIDDEN + col] =
                make_float2(c[mi][nf][0] + bv0, c[mi][nf][1] + bv1);
            int r1 = r0 + 8;
            int b1i = r1 >> 9, t1 = r1 & 511;
            *(float2*)&g_X[g][t1][b1i * HIDDEN + col] =
                make_float2(c[mi][nf][2] + bv0, c[mi][nf][3] + bv1);
        }
    }
}

// ---------------- Kernel 2: persistent HMMA recurrence -----------------------------
#define STRE 264
#define STRB (STRE * 2)
#define OFF_AHI 0
#define OFF_ALO (OFF_AHI + 128 * STRB)
#define OFF_BHI (OFF_ALO + 128 * STRB)
#define OFF_BLO (OFF_BHI + 64 * STRB)
#define SMEM_PERSIST (OFF_BLO + 64 * STRB)

__global__ __launch_bounds__(256, 1) void recurrent_persistent()
{
    extern __shared__ char smem[];
    const u32 sbase = smem_u32(smem);
    const int tid  = threadIdx.x;
    const int wid  = tid >> 5, lane = tid & 31;
    const int cta  = blockIdx.x;
    const int ks   = cta & 3;
    const int n0   = (cta >> 2) * 64;
    const int kbase = ks * 256;

    // resident B tiles (weights)
#pragma unroll
    for (int it = 0; it < 8; it++) {
        int idx = tid + it * 256;
        int row = idx >> 5;
        int c   = idx & 31;
        long src = (long)(n0 + row) * HIDDEN + kbase + c * 8;
        *(uint4*)(smem + OFF_BHI + row * STRB + c * 16) = *(const uint4*)&g_Wt_hi[src];
        *(uint4*)(smem + OFF_BLO + row * STRB + c * 16) = *(const uint4*)&g_Wt_lo[src];
    }
    __syncthreads();

    const int wm = wid & 3, wn = wid >> 2;
    const int m_base = wm * 32, n_base = wn * 32;
    const int grp = lane >> 2, tg = lane & 3;

    const u32 a_row = (u32)(lane & 15);
    const u32 b_row = (u32)((((lane >> 3) & 1) * 8) + (lane & 7));
    const u32 khalf = (u32)((lane >> 4) * 16);

    const u32 aHi0 = sbase + OFF_AHI + (m_base + a_row) * STRB + khalf;
    const u32 aLo0 = sbase + OFF_ALO + (m_base + a_row) * STRB + khalf;
    const u32 bHi0 = sbase + OFF_BHI + (n_base + b_row) * STRB + khalf;
    const u32 bLo0 = sbase + OFF_BLO + (n_base + b_row) * STRB + khalf;

    // reduce-phase assignment: 4 consecutive h elements per thread (row-contiguous)
    const int ubase = (cta * 256 + tid) * 4;
    const int um = ubase >> 10;
    const int uj = ubase & 1023;

    // register-carried hidden state: this thread owns h[ubase..ubase+3] every step
    float hreg[4] = {0.0f, 0.0f, 0.0f, 0.0f};

    unsigned gen = 0;

    for (int t = 0; t < SEQL; t++) {
        const int par = t & 1;
        const __nv_bfloat16* hhi = g_hhi[par];
        const __nv_bfloat16* hlo = g_hlo[par];

        // ---- issue cp.async A staging: two K halves of 128 cols each ----
#pragma unroll
        for (int h = 0; h < 2; h++) {
#pragma unroll
            for (int it = 0; it < 8; it++) {
                int idx = tid + it * 256;        // 0..2047
                int row = idx >> 4;              // 0..127
                int c   = (idx & 15) + h * 16;   // 16B-chunk id along k
                long src = (long)row * HIDDEN + kbase + c * 8;
                u32 dst = sbase + OFF_AHI + row * STRB + c * 16;
                CP16(dst, (const void*)&hhi[src]);
                CP16(dst + (OFF_ALO - OFF_AHI), (const void*)&hlo[src]);
            }
            CP_COMMIT();
        }

        // prefetch this step's input-projection values (DRAM) for the reduce phase
        float4 zs = *(const float4*)&g_X[0][t][um * HIDDEN + uj];
        float4 hs = *(const float4*)&g_X[1][t][um * HIDDEN + uj];

        float c[2][4][4];
#pragma unroll
        for (int mi = 0; mi < 2; mi++)
#pragma unroll
            for (int nf = 0; nf < 4; nf++)
#pragma unroll
                for (int r = 0; r < 4; r++) c[mi][nf][r] = 0.0f;

        // ---- MMA: half 0 after wait_group 1; half 1 overlapped ----
#pragma unroll
        for (int half = 0; half < 2; half++) {
            if (half == 0) { CP_WAIT1(); }
            else           { CP_WAIT0(); }
            __syncthreads();
#pragma unroll
            for (int kk = 0; kk < 8; kk++) {
                const int k16 = half * 8 + kk;
                const u32 kb = (u32)(k16 * 32);
                u32 ah[2][4], al[2][4], bhv[2][4], blv[2][4];
#pragma unroll
                for (int mi = 0; mi < 2; mi++) {
                    ldmx4(ah[mi], aHi0 + mi * 16 * STRB + kb);
                    ldmx4(al[mi], aLo0 + mi * 16 * STRB + kb);
                }
#pragma unroll
                for (int nb = 0; nb < 2; nb++) {
                    ldmx4(bhv[nb], bHi0 + nb * 16 * STRB + kb);
                    ldmx4(blv[nb], bLo0 + nb * 16 * STRB + kb);
                }
#pragma unroll
                for (int mi = 0; mi < 2; mi++) {
#pragma unroll
                    for (int nf = 0; nf < 4; nf++) {
                        int nb = nf >> 1, hf = nf & 1;
                        mma16816(c[mi][nf], ah[mi], bhv[nb][hf], bhv[nb][2 + hf]);
                        mma16816(c[mi][nf], ah[mi], blv[nb][hf], blv[nb][2 + hf]);
                        mma16816(c[mi][nf], al[mi], bhv[nb][hf], bhv[nb][2 + hf]);
                    }
                }
            }
        }

        // ---- epilogue: partials -> g_P (L1-bypass) ----
#pragma unroll
        for (int mi = 0; mi < 2; mi++) {
#pragma unroll
            for (int nf = 0; nf < 4; nf++) {
                int row = m_base + mi * 16 + grp;
                int col = n0 + n_base + nf * 8 + tg * 2;
                __stcg((float2*)&g_P[ks][row * NTOT + col],
                       make_float2(c[mi][nf][0], c[mi][nf][1]));
                __stcg((float2*)&g_P[ks][(row + 8) * NTOT + col],
                       make_float2(c[mi][nf][2], c[mi][nf][3]));
            }
        }

        full_barrier(cta, ++gen);

        // ---- reduce + gate + update: one float4 per thread, fully coalesced ----
        {
#pragma unroll
            for (int s = 0; s < KSPLIT; s++) {
                float4 pz = __ldcg((const float4*)&g_P[s][um * NTOT + uj]);
                float4 ph = __ldcg((const float4*)&g_P[s][um * NTOT + 1024 + uj]);
                zs.x += pz.x; zs.y += pz.y; zs.z += pz.z; zs.w += pz.w;
                hs.x += ph.x; hs.y += ph.y; hs.z += ph.z; hs.w += ph.w;
            }
            float zv[4] = {zs.x, zs.y, zs.z, zs.w};
            float hv[4] = {hs.x, hs.y, hs.z, hs.w};
            unsigned short hiu[4], lou[4];
#pragma unroll
            for (int i = 0; i < 4; i++) {
                float z  = 1.0f / (1.0f + __expf(-zv[i]));
                float hn = hreg[i] + z * (tanhf(hv[i]) - hreg[i]);
                hreg[i] = hn;                              // carry in registers
                __nv_bfloat16 hb = __float2bfloat16_rn(hn);
                __nv_bfloat16 lb = __float2bfloat16_rn(hn - __bfloat162float(hb));
                hiu[i] = __bfloat16_as_ushort(hb);
                lou[i] = __bfloat16_as_ushort(lb);
            }
            ull hpack = (ull)hiu[0] | ((ull)hiu[1] << 16) | ((ull)hiu[2] << 32) | ((ull)hiu[3] << 48);
            ull lpack = (ull)lou[0] | ((ull)lou[1] << 16) | ((ull)lou[2] << 32) | ((ull)lou[3] << 48);
            __stcg((ull*)&g_hhi[par ^ 1][um * HIDDEN + uj], hpack);
            __stcg((ull*)&g_hlo[par ^ 1][um * HIDDEN + uj], lpack);
        }

        full_barrier(cta, ++gen);
    }
}

// ---------------- Kernel 3: final FC -------------------------------------------------
__global__ __launch_bounds__(128) void fc_kernel(
    const float* __restrict__ Wfc,
    const float* __restrict__ bfc,
    float* __restrict__ out)
{
    extern __shared__ float hsm[];
    const int b0 = blockIdx.y * 16;
    const int tid = threadIdx.x;

    for (int i = tid; i < 16 * HIDDEN / 4; i += 128) {
        ull hi4 = *(const ull*)&g_hhi[0][b0 * HIDDEN + i * 4];
        ull lo4 = *(const ull*)&g_hlo[0][b0 * HIDDEN + i * 4];
        float4 v;
        float* vp = (float*)&v;
#pragma unroll
        for (int j = 0; j < 4; j++) {
            __nv_bfloat16 a = __ushort_as_bfloat16((unsigned short)(hi4 >> (16 * j)));
            __nv_bfloat16 b = __ushort_as_bfloat16((unsigned short)(lo4 >> (16 * j)));
            vp[j] = __bfloat162float(a) + __bfloat162float(b);
        }
        ((float4*)hsm)[i] = v;
    }
    __syncthreads();

    const int n = blockIdx.x * 128 + tid;
    if (n >= NCLS) return;

    float acc[16];
#pragma unroll
    for (int i = 0; i < 16; i++) acc[i] = 0.0f;

    for (int k = 0; k < HIDDEN; k += 4) {
        float w0 = Wfc[(long)(k + 0) * NCLS + n];
        float w1 = Wfc[(long)(k + 1) * NCLS + n];
        float w2 = Wfc[(long)(k + 2) * NCLS + n];
        float w3 = Wfc[(long)(k + 3) * NCLS + n];
#pragma unroll
        for (int i = 0; i < 16; i++) {
            float4 h4 = *(const float4*)&hsm[i * HIDDEN + k];
            acc[i] += w0 * h4.x + w1 * h4.y + w2 * h4.z + w3 * h4.w;
        }
    }
    float bv = bfc[n];
#pragma unroll
    for (int i = 0; i < 16; i++)
        out[(long)(b0 + i) * NCLS + n] = acc[i] + bv;
}

// ---------------- launch ---------------------------------------------------------------
extern "C" void kernel_launch(void* const* d_in, const int* in_sizes, int n_in,
                              void* d_out, int out_size)
{
    const int*   x   = (const int*)d_in[0];
    const float* emb = (const float*)d_in[1];
    const float* Wz  = (const float*)d_in[2];
    const float* bz  = (const float*)d_in[3];
    const float* Wh  = (const float*)d_in[4];
    const float* bh  = (const float*)d_in[5];
    const float* Wfc = (const float*)d_in[6];
    const float* bfc = (const float*)d_in[7];
    float* out = (float*)d_out;

    cudaFuncSetAttribute(gemm_embed_mma,
                         cudaFuncAttributeMaxDynamicSharedMemorySize, SMEM_EMBED);
    cudaFuncSetAttribute(recurrent_persistent,
                         cudaFuncAttributeMaxDynamicSharedMemorySize, SMEM_PERSIST);
    cudaFuncSetAttribute(fc_kernel,
                         cudaFuncAttributeMaxDynamicSharedMemorySize, 16 * HIDDEN * 4);

    init_kernel<<<512, 256>>>();
    conv_emb<<<16000, 256>>>(emb);
    prep_weights<<<dim3(32, 64), dim3(32, 8)>>>(Wz, Wh);
    prep_win<<<dim3(16, 64), dim3(32, 8)>>>(Wz, Wh);
    gemm_embed_mma<<<dim3(16, 512), 256, SMEM_EMBED>>>(x, bz, bh);
    recurrent_persistent<<<NCTA, 256, SMEM_PERSIST>>>();
    fc_kernel<<<dim3(8, 8), 128, 16 * HIDDEN * 4>>>(Wfc, bfc, out);
}